// round 1
// baseline (speedup 1.0000x reference)
#include <cuda_runtime.h>

// ---------------------------------------------------------------------------
// SimpleGCN on GB300/B200-class (sm_100a). fp32 throughout.
//
// Math restructure: norm(e) = dis[src]*dis[dst] factors, so:
//   s[n]   = (in @ W)[n] * dis[n]                     (GEMM epilogue scale)
//   acc[v] = sum_{e: dst(e)=v} s[src(e)]              (pure scatter-add)
//   h[v]   = relu((acc[v] + s[v]) * dis[v] + b)       (self-loop + dst scale)
// ---------------------------------------------------------------------------

#define NN 100000
#define EE 1600000
#define HF 64
#define GG 64

__device__ float g_dis[NN];          // rsqrt(deg), deg includes self-loop
__device__ float g_s  [NN * HF];     // (in@W)*dis[src]
__device__ float g_acc[NN * HF];     // scatter accumulator
__device__ float g_h  [NN * HF];     // layer output
__device__ float g_pool[GG * HF];    // per-graph pooled sums

// ---------------------------------------------------------------------------
__global__ void k_deg_init(int n) {
    int i = blockIdx.x * blockDim.x + threadIdx.x;
    if (i < n) g_dis[i] = 1.0f;                  // self loop
}

__global__ void k_deg_count(const int* __restrict__ dst, int e) {
    int i = blockIdx.x * blockDim.x + threadIdx.x;
    if (i < e) atomicAdd(&g_dis[dst[i]], 1.0f);
}

__global__ void k_deg_rsqrt(int n) {
    int i = blockIdx.x * blockDim.x + threadIdx.x;
    if (i < n) g_dis[i] = rsqrtf(g_dis[i]);
}

// ---------------------------------------------------------------------------
__device__ __forceinline__ void fma4(float4& a, float k, float4 w) {
    a.x = fmaf(k, w.x, a.x);
    a.y = fmaf(k, w.y, a.y);
    a.z = fmaf(k, w.z, a.z);
    a.w = fmaf(k, w.w, a.w);
}

// s[n] = (in[n] @ W) * dis[n].  4 threads per node, 16 outputs each.
__global__ void k_gemm_scale(const float* __restrict__ in,
                             const float* __restrict__ W, int n) {
    __shared__ float Ws[64 * 64];
    for (int i = threadIdx.x; i < 64 * 64; i += blockDim.x) Ws[i] = W[i];
    __syncthreads();

    int gid  = blockIdx.x * blockDim.x + threadIdx.x;
    int node = gid >> 2;
    int part = gid & 3;                       // output cols [part*16, part*16+16)
    if (node >= n) return;

    float4 a0 = {0,0,0,0}, a1 = {0,0,0,0}, a2 = {0,0,0,0}, a3 = {0,0,0,0};
    const float*  xr  = in + node * 64;
    const float4* Ws4 = reinterpret_cast<const float4*>(Ws);

#pragma unroll 8
    for (int k = 0; k < 64; k++) {
        float xk = __ldg(xr + k);
        const float4* wr = Ws4 + k * 16 + part * 4;
        fma4(a0, xk, wr[0]);
        fma4(a1, xk, wr[1]);
        fma4(a2, xk, wr[2]);
        fma4(a3, xk, wr[3]);
    }
    float dn = g_dis[node];
    a0.x *= dn; a0.y *= dn; a0.z *= dn; a0.w *= dn;
    a1.x *= dn; a1.y *= dn; a1.z *= dn; a1.w *= dn;
    a2.x *= dn; a2.y *= dn; a2.z *= dn; a2.w *= dn;
    a3.x *= dn; a3.y *= dn; a3.z *= dn; a3.w *= dn;

    float4* op = reinterpret_cast<float4*>(g_s + node * 64 + part * 16);
    op[0] = a0; op[1] = a1; op[2] = a2; op[3] = a3;
}

// ---------------------------------------------------------------------------
__global__ void k_zero(int n4) {                 // zero g_acc (n4 float4s)
    int i = blockIdx.x * blockDim.x + threadIdx.x;
    if (i < n4) reinterpret_cast<float4*>(g_acc)[i] = make_float4(0,0,0,0);
}

// acc[dst] += s[src].  16 threads (float4 lanes) per edge, grid-stride.
__global__ void k_scatter(const int* __restrict__ src,
                          const int* __restrict__ dst, long total) {
    long stride = (long)gridDim.x * blockDim.x;
    for (long idx = (long)blockIdx.x * blockDim.x + threadIdx.x;
         idx < total; idx += stride) {
        int e = (int)(idx >> 4);
        int c = (int)(idx & 15);
        int u = __ldg(src + e);
        int v = __ldg(dst + e);
        float4 val = __ldg(reinterpret_cast<const float4*>(g_s) + u * 16 + c);
        float* p = g_acc + (long)v * 64 + c * 4;
        asm volatile("red.global.add.v4.f32 [%0], {%1,%2,%3,%4};"
                     :: "l"(p), "f"(val.x), "f"(val.y), "f"(val.z), "f"(val.w)
                     : "memory");
    }
}

// h[n] = relu((acc[n] + s[n]) * dis[n] + b)
__global__ void k_finalize(const float* __restrict__ b, int n) {
    int idx = blockIdx.x * blockDim.x + threadIdx.x;   // over n*16 float4s
    if (idx >= n * 16) return;
    int node = idx >> 4;
    int c    = idx & 15;
    float dn = g_dis[node];
    float4 a  = reinterpret_cast<const float4*>(g_acc)[idx];
    float4 sv = reinterpret_cast<const float4*>(g_s)[idx];
    float4 bv = __ldg(reinterpret_cast<const float4*>(b) + c);
    float4 r;
    r.x = fmaxf(fmaf(a.x + sv.x, dn, bv.x), 0.0f);
    r.y = fmaxf(fmaf(a.y + sv.y, dn, bv.y), 0.0f);
    r.z = fmaxf(fmaf(a.z + sv.z, dn, bv.z), 0.0f);
    r.w = fmaxf(fmaf(a.w + sv.w, dn, bv.w), 0.0f);
    reinterpret_cast<float4*>(g_h)[idx] = r;
}

// ---------------------------------------------------------------------------
// Per-graph sum pool. gids sorted; block g binary-searches its segment.
__global__ void k_pool(const int* __restrict__ gids, int n) {
    int g = blockIdx.x;
    int lo = 0, hi = n;
    while (lo < hi) { int m = (lo + hi) >> 1; if (gids[m] < g) lo = m + 1; else hi = m; }
    int start = lo;
    lo = start; hi = n;
    while (lo < hi) { int m = (lo + hi) >> 1; if (gids[m] < g + 1) lo = m + 1; else hi = m; }
    int end = lo;

    int f = threadIdx.x & 63;
    int r = threadIdx.x >> 6;                 // 0..3
    float sum = 0.0f;
    for (int i = start + r; i < end; i += 4) sum += g_h[i * 64 + f];

    __shared__ float red[4][64];
    red[r][f] = sum;
    __syncthreads();
    if (r == 0) g_pool[g * 64 + f] = red[0][f] + red[1][f] + red[2][f] + red[3][f];
}

// ---------------------------------------------------------------------------
// Head MLP: one block, 256 threads. G=64 rows, tiny.
__global__ void k_head(const float* __restrict__ gfeat,
                       const float* __restrict__ gw, const float* __restrict__ gb,
                       const float* __restrict__ l1w, const float* __restrict__ l1b,
                       const float* __restrict__ l2w, const float* __restrict__ l2b,
                       const float* __restrict__ l3w, const float* __restrict__ l3b,
                       const float* __restrict__ l4w, const float* __restrict__ l4b,
                       float* __restrict__ out) {
    __shared__ float A[64][97];      // holds [z1 | gx] (96 cols), then z3
    __shared__ float Bm[64][65];     // holds z2
    int t = threadIdx.x;

    // z1 = relu(pool @ l1w + b)
    for (int e = t; e < 64 * 64; e += 256) {
        int i = e >> 6, j = e & 63;
        float sum = l1b[j];
        for (int k = 0; k < 64; k++) sum = fmaf(g_pool[i * 64 + k], l1w[k * 64 + j], sum);
        A[i][j] = fmaxf(sum, 0.0f);
    }
    // gx = relu(gfeat @ gw + gb)  -> A[:, 64:96]
    for (int e = t; e < 64 * 32; e += 256) {
        int i = e >> 5, j = e & 31;
        float sum = gb[j];
        for (int k = 0; k < 32; k++) sum = fmaf(gfeat[i * 32 + k], gw[k * 32 + j], sum);
        A[i][64 + j] = fmaxf(sum, 0.0f);
    }
    __syncthreads();
    // z2 = relu([z1|gx] @ l2w + b)
    for (int e = t; e < 64 * 64; e += 256) {
        int i = e >> 6, j = e & 63;
        float sum = l2b[j];
        for (int k = 0; k < 96; k++) sum = fmaf(A[i][k], l2w[k * 64 + j], sum);
        Bm[i][j] = fmaxf(sum, 0.0f);
    }
    __syncthreads();
    // z3 = relu(z2 @ l3w + b)
    for (int e = t; e < 64 * 64; e += 256) {
        int i = e >> 6, j = e & 63;
        float sum = l3b[j];
        for (int k = 0; k < 64; k++) sum = fmaf(Bm[i][k], l3w[k * 64 + j], sum);
        A[i][j] = fmaxf(sum, 0.0f);
    }
    __syncthreads();
    // out = z3 @ l4w + b
    if (t < 64) {
        float sum = l4b[0];
        for (int k = 0; k < 64; k++) sum = fmaf(A[t][k], l4w[k], sum);
        out[t] = sum;
    }
}

// ---------------------------------------------------------------------------
extern "C" void kernel_launch(void* const* d_in, const int* in_sizes, int n_in,
                              void* d_out, int out_size) {
    const float* x     = (const float*)d_in[0];
    const float* gfeat = (const float*)d_in[1];
    const float* cw[3] = {(const float*)d_in[2], (const float*)d_in[4], (const float*)d_in[6]};
    const float* cb[3] = {(const float*)d_in[3], (const float*)d_in[5], (const float*)d_in[7]};
    const float* l1w = (const float*)d_in[8];
    const float* l1b = (const float*)d_in[9];
    const float* gw  = (const float*)d_in[10];
    const float* gb  = (const float*)d_in[11];
    const float* l2w = (const float*)d_in[12];
    const float* l2b = (const float*)d_in[13];
    const float* l3w = (const float*)d_in[14];
    const float* l3b = (const float*)d_in[15];
    const float* l4w = (const float*)d_in[16];
    const float* l4b = (const float*)d_in[17];
    const int*   ei   = (const int*)d_in[18];
    const int*   gids = (const int*)d_in[19];
    float* out = (float*)d_out;

    int N = in_sizes[19];
    int E = in_sizes[18] / 2;
    const int* src = ei;
    const int* dst = ei + E;

    const int T = 256;
    int nb_n   = (N + T - 1) / T;
    int nb_e   = (E + T - 1) / T;
    int nb_4n  = (4 * N + T - 1) / T;            // gemm: 4 threads/node
    int nb_16n = (16 * N + T - 1) / T;           // float4 per-element passes
    long sc_total = (long)E * 16;
    int nb_sc  = 16384;                          // grid-stride scatter

    // --- degree / normalization (recomputed every launch; cheap) ---
    k_deg_init<<<nb_n, T>>>(N);
    k_deg_count<<<nb_e, T>>>(dst, E);
    k_deg_rsqrt<<<nb_n, T>>>(N);

    // --- 3 GCN conv layers ---
    const float* in_ptr = x;
    for (int l = 0; l < 3; l++) {
        k_gemm_scale<<<nb_4n, T>>>(in_ptr, cw[l], N);
        k_zero<<<nb_16n, T>>>(N * 16);
        k_scatter<<<nb_sc, T>>>(src, dst, sc_total);
        k_finalize<<<nb_16n, T>>>(cb[l], N);
        in_ptr = nullptr;  // set below
        // subsequent layers read g_h directly
        static float* dummy = nullptr; (void)dummy;
        in_ptr = (const float*)nullptr;
        // pass g_h via symbol: easiest is a device-pointer-free design, so
        // use a tiny trampoline: layer >0 uses g_h. We fetch its address once.
        void* hptr = nullptr;
        cudaGetSymbolAddress(&hptr, g_h);
        in_ptr = (const float*)hptr;
    }

    // --- pool + head ---
    k_pool<<<GG, T>>>(gids, N);
    k_head<<<1, T>>>(gfeat, gw, gb, l1w, l1b, l2w, l2b, l3w, l3b, l4w, l4b, out);
}

// round 2
// speedup vs baseline: 1.4162x; 1.4162x over previous
#include <cuda_runtime.h>

// ---------------------------------------------------------------------------
// SimpleGCN, sm_100a, fp32 (f32x2 packed FMA in the GEMM).
//
//   s[n]   = (in @ W)[n] * dis[n]           (GEMM epilogue; also inits acc)
//   acc[v] = s[v] + sum_{e: dst=v} s[src]   (self-loop fused; scatter adds)
//   next-layer input (on the fly): relu(acc[n]*dis[n] + b_prev)
// ---------------------------------------------------------------------------

#define NN 100000
#define GG 64

__device__ float g_dis[NN];
__device__ float g_s  [NN * 64];
__device__ float g_acc[NN * 64];
__device__ float g_pool[GG * 64];

// --------------------------- degree / normalization ------------------------
__global__ void k_deg_init(int n) {
    int i = blockIdx.x * blockDim.x + threadIdx.x;
    if (i < n) g_dis[i] = 1.0f;                  // self loop
}
__global__ void k_deg_count(const int* __restrict__ dst, int e) {
    int i = blockIdx.x * blockDim.x + threadIdx.x;
    if (i < e) atomicAdd(&g_dis[dst[i]], 1.0f);
}
__global__ void k_deg_rsqrt(int n) {
    int i = blockIdx.x * blockDim.x + threadIdx.x;
    if (i < n) g_dis[i] = rsqrtf(g_dis[i]);
}

// --------------------------- packed f32x2 helpers --------------------------
__device__ __forceinline__ unsigned long long pk2(float x) {
    unsigned long long r;
    asm("mov.b64 %0, {%1, %1};" : "=l"(r) : "f"(x));
    return r;
}
__device__ __forceinline__ void ffma2(unsigned long long& d,
                                      unsigned long long a,
                                      unsigned long long b) {
    asm("fma.rn.f32x2 %0, %1, %2, %0;" : "+l"(d) : "l"(a), "l"(b));
}
__device__ __forceinline__ float2 up2(unsigned long long v) {
    float2 r;
    asm("mov.b64 {%0, %1}, %2;" : "=f"(r.x), "=f"(r.y) : "l"(v));
    return r;
}

// --------------------------- fused GEMM ------------------------------------
// One thread per node. Computes s = (in' @ W) * dis[node], where
//   FIRST:  in' = in row (raw x)
//   !FIRST: in' = relu(in_row * dis[node] + bias_prev)   (in = g_acc)
// Writes s to g_s AND g_acc (self-loop init). 64 accumulators as 32 f32x2.
template<bool FIRST>
__global__ void __launch_bounds__(256)
k_gemm(const float* __restrict__ in, const float* __restrict__ W,
       const float* __restrict__ bias_prev, int n) {
    __shared__ ulonglong2 Ws2[64 * 16];          // W row-major, 16B granules
    __shared__ float bs[64];
    {
        const float4* W4 = reinterpret_cast<const float4*>(W);
        float4* S4 = reinterpret_cast<float4*>(Ws2);
#pragma unroll
        for (int i = threadIdx.x; i < 64 * 16; i += 256) S4[i] = W4[i];
        if (!FIRST && threadIdx.x < 64) bs[threadIdx.x] = bias_prev[threadIdx.x];
    }
    __syncthreads();

    int node = blockIdx.x * blockDim.x + threadIdx.x;
    if (node >= n) return;

    float dn = g_dis[node];

    unsigned long long acc[32];
#pragma unroll
    for (int j = 0; j < 32; j++) acc[j] = 0ull;

    const float4* xr4 = reinterpret_cast<const float4*>(in + node * 64);

#pragma unroll 2
    for (int k4 = 0; k4 < 16; k4++) {
        float4 xv = __ldg(xr4 + k4);
        if (!FIRST) {
            xv.x = fmaxf(fmaf(xv.x, dn, bs[k4 * 4 + 0]), 0.0f);
            xv.y = fmaxf(fmaf(xv.y, dn, bs[k4 * 4 + 1]), 0.0f);
            xv.z = fmaxf(fmaf(xv.z, dn, bs[k4 * 4 + 2]), 0.0f);
            xv.w = fmaxf(fmaf(xv.w, dn, bs[k4 * 4 + 3]), 0.0f);
        }
        const float xs[4] = {xv.x, xv.y, xv.z, xv.w};
#pragma unroll
        for (int kk = 0; kk < 4; kk++) {
            int k = k4 * 4 + kk;
            unsigned long long xk2 = pk2(xs[kk]);
#pragma unroll
            for (int j = 0; j < 16; j++) {
                ulonglong2 w = Ws2[k * 16 + j];
                ffma2(acc[2 * j],     xk2, w.x);
                ffma2(acc[2 * j + 1], xk2, w.y);
            }
        }
    }

    float4* sp = reinterpret_cast<float4*>(g_s   + node * 64);
    float4* ap = reinterpret_cast<float4*>(g_acc + node * 64);
#pragma unroll
    for (int j = 0; j < 16; j++) {
        float2 lo = up2(acc[2 * j]);
        float2 hi = up2(acc[2 * j + 1]);
        float4 v = make_float4(lo.x * dn, lo.y * dn, hi.x * dn, hi.y * dn);
        sp[j] = v;
        ap[j] = v;
    }
}

// --------------------------- edge scatter ----------------------------------
// acc[dst] += s[src]. 16 lanes (float4 each) per edge.
__global__ void k_scatter(const int* __restrict__ src,
                          const int* __restrict__ dst, long total) {
    long idx = (long)blockIdx.x * blockDim.x + threadIdx.x;
    if (idx >= total) return;
    int e = (int)(idx >> 4);
    int c = (int)(idx & 15);
    int u = __ldg(src + e);
    int v = __ldg(dst + e);
    float4 val = __ldg(reinterpret_cast<const float4*>(g_s) + u * 16 + c);
    float* p = g_acc + (long)v * 64 + c * 4;
    asm volatile("red.global.add.v4.f32 [%0], {%1,%2,%3,%4};"
                 :: "l"(p), "f"(val.x), "f"(val.y), "f"(val.z), "f"(val.w)
                 : "memory");
}

// --------------------------- pool (applies last finalize) ------------------
// pool[g][f] = sum over nodes in graph g of relu(acc*dis + b2).
__global__ void k_pool(const int* __restrict__ gids,
                       const float* __restrict__ b2, int n) {
    int g = blockIdx.x;
    int lo = 0, hi = n;
    while (lo < hi) { int m = (lo + hi) >> 1; if (gids[m] < g) lo = m + 1; else hi = m; }
    int start = lo;
    lo = start; hi = n;
    while (lo < hi) { int m = (lo + hi) >> 1; if (gids[m] < g + 1) lo = m + 1; else hi = m; }
    int end = lo;

    int f = threadIdx.x & 63;
    int r = threadIdx.x >> 6;                    // 0..3
    float bf = b2[f];
    float sum = 0.0f;
    for (int i = start + r; i < end; i += 4) {
        float d = g_dis[i];
        sum += fmaxf(fmaf(g_acc[i * 64 + f], d, bf), 0.0f);
    }
    __shared__ float red[4][64];
    red[r][f] = sum;
    __syncthreads();
    if (r == 0) g_pool[g * 64 + f] = red[0][f] + red[1][f] + red[2][f] + red[3][f];
}

// --------------------------- head MLP --------------------------------------
__global__ void k_head(const float* __restrict__ gfeat,
                       const float* __restrict__ gw, const float* __restrict__ gb,
                       const float* __restrict__ l1w, const float* __restrict__ l1b,
                       const float* __restrict__ l2w, const float* __restrict__ l2b,
                       const float* __restrict__ l3w, const float* __restrict__ l3b,
                       const float* __restrict__ l4w, const float* __restrict__ l4b,
                       float* __restrict__ out) {
    __shared__ float A[64][97];
    __shared__ float Bm[64][65];
    int t = threadIdx.x;

    for (int e = t; e < 64 * 64; e += 256) {          // z1
        int i = e >> 6, j = e & 63;
        float sum = l1b[j];
        for (int k = 0; k < 64; k++) sum = fmaf(g_pool[i * 64 + k], l1w[k * 64 + j], sum);
        A[i][j] = fmaxf(sum, 0.0f);
    }
    for (int e = t; e < 64 * 32; e += 256) {          // gx
        int i = e >> 5, j = e & 31;
        float sum = gb[j];
        for (int k = 0; k < 32; k++) sum = fmaf(gfeat[i * 32 + k], gw[k * 32 + j], sum);
        A[i][64 + j] = fmaxf(sum, 0.0f);
    }
    __syncthreads();
    for (int e = t; e < 64 * 64; e += 256) {          // z2
        int i = e >> 6, j = e & 63;
        float sum = l2b[j];
        for (int k = 0; k < 96; k++) sum = fmaf(A[i][k], l2w[k * 64 + j], sum);
        Bm[i][j] = fmaxf(sum, 0.0f);
    }
    __syncthreads();
    for (int e = t; e < 64 * 64; e += 256) {          // z3
        int i = e >> 6, j = e & 63;
        float sum = l3b[j];
        for (int k = 0; k < 64; k++) sum = fmaf(Bm[i][k], l3w[k * 64 + j], sum);
        A[i][j] = fmaxf(sum, 0.0f);
    }
    __syncthreads();
    if (t < 64) {                                     // out
        float sum = l4b[0];
        for (int k = 0; k < 64; k++) sum = fmaf(A[t][k], l4w[k], sum);
        out[t] = sum;
    }
}

// ---------------------------------------------------------------------------
extern "C" void kernel_launch(void* const* d_in, const int* in_sizes, int n_in,
                              void* d_out, int out_size) {
    const float* x     = (const float*)d_in[0];
    const float* gfeat = (const float*)d_in[1];
    const float* cw[3] = {(const float*)d_in[2], (const float*)d_in[4], (const float*)d_in[6]};
    const float* cb[3] = {(const float*)d_in[3], (const float*)d_in[5], (const float*)d_in[7]};
    const float* l1w = (const float*)d_in[8];
    const float* l1b = (const float*)d_in[9];
    const float* gw  = (const float*)d_in[10];
    const float* gb  = (const float*)d_in[11];
    const float* l2w = (const float*)d_in[12];
    const float* l2b = (const float*)d_in[13];
    const float* l3w = (const float*)d_in[14];
    const float* l3b = (const float*)d_in[15];
    const float* l4w = (const float*)d_in[16];
    const float* l4b = (const float*)d_in[17];
    const int*   ei   = (const int*)d_in[18];
    const int*   gids = (const int*)d_in[19];
    float* out = (float*)d_out;

    int N = in_sizes[19];
    int E = in_sizes[18] / 2;
    const int* src = ei;
    const int* dst = ei + E;

    void* accp = nullptr;
    cudaGetSymbolAddress(&accp, g_acc);
    const float* acc_in = (const float*)accp;

    const int T = 256;
    int nb_n  = (N + T - 1) / T;
    int nb_e  = (E + T - 1) / T;
    long sc_total = (long)E * 16;
    int nb_sc = (int)((sc_total + T - 1) / T);

    // degree / normalization
    k_deg_init<<<nb_n, T>>>(N);
    k_deg_count<<<nb_e, T>>>(dst, E);
    k_deg_rsqrt<<<nb_n, T>>>(N);

    // layer 0
    k_gemm<true ><<<nb_n, T>>>(x,      cw[0], nullptr, N);
    k_scatter<<<nb_sc, T>>>(src, dst, sc_total);
    // layer 1
    k_gemm<false><<<nb_n, T>>>(acc_in, cw[1], cb[0], N);
    k_scatter<<<nb_sc, T>>>(src, dst, sc_total);
    // layer 2
    k_gemm<false><<<nb_n, T>>>(acc_in, cw[2], cb[1], N);
    k_scatter<<<nb_sc, T>>>(src, dst, sc_total);

    // pool (applies relu(acc*dis+b2)) + head
    k_pool<<<GG, T>>>(gids, cb[2], N);
    k_head<<<1, T>>>(gfeat, gw, gb, l1w, l1b, l2w, l2b, l3w, l3b, l4w, l4b, out);
}

// round 3
// speedup vs baseline: 1.7294x; 1.2211x over previous
#include <cuda_runtime.h>

// ---------------------------------------------------------------------------
// SimpleGCN, sm_100a. fp32, f32x2 packed FMA GEMM, CSR gather (no atomics in
// the per-layer hot path).
//
//   s[n]   = (in' @ W)[n] * dis[n]                  (GEMM, writes g_s)
//   acc[v] = s[v] + sum_{in-edges} s[u]             (CSR gather, writes g_acc)
//   in'    = relu(acc * dis + b_prev)               (fused into next GEMM/pool)
// ---------------------------------------------------------------------------

#define NN 100000
#define EE 1600000
#define GG 64

__device__ float g_dis [NN];
__device__ int   g_degi[NN];
__device__ int   g_rowptr[NN + 1];
__device__ int   g_cursor[NN];
__device__ int   g_bsum[512];
__device__ int   g_csr[EE];
__device__ float g_s  [NN * 64];
__device__ float g_acc[NN * 64];
__device__ float g_pool[GG * 64];

// --------------------------- degree + dis ----------------------------------
__global__ void k_deg0(int n) {
    int i = blockIdx.x * blockDim.x + threadIdx.x;
    if (i < n) g_degi[i] = 0;
}
__global__ void k_degc(const int* __restrict__ dst, int e) {
    int i = blockIdx.x * blockDim.x + threadIdx.x;
    if (i < e) atomicAdd(&g_degi[dst[i]], 1);
}
__global__ void k_dis(int n) {
    int i = blockIdx.x * blockDim.x + threadIdx.x;
    if (i < n) g_dis[i] = rsqrtf((float)g_degi[i] + 1.0f);
}

// --------------------------- exclusive scan (rowptr) -----------------------
__global__ void k_scan1(int n) {               // per-block scan of g_degi
    __shared__ int s[256];
    int b = blockIdx.x, t = threadIdx.x;
    int i = b * 256 + t;
    int v = (i < n) ? g_degi[i] : 0;
    s[t] = v;
    __syncthreads();
#pragma unroll
    for (int off = 1; off < 256; off <<= 1) {
        int add = (t >= off) ? s[t - off] : 0;
        __syncthreads();
        s[t] += add;
        __syncthreads();
    }
    if (i < n) g_rowptr[i] = s[t] - v;         // exclusive within block
    if (t == 255) g_bsum[b] = s[255];
}
__global__ void k_scan2(int nb) {              // single block: scan block sums
    __shared__ int s[512];
    int t = threadIdx.x;
    int v = (t < nb) ? g_bsum[t] : 0;
    s[t] = v;
    __syncthreads();
#pragma unroll
    for (int off = 1; off < 512; off <<= 1) {
        int add = (t >= off) ? s[t - off] : 0;
        __syncthreads();
        s[t] += add;
        __syncthreads();
    }
    if (t < nb) g_bsum[t] = s[t] - v;          // exclusive
}
__global__ void k_scan3(int n, int e) {        // add block offsets; init cursor
    int i = blockIdx.x * blockDim.x + threadIdx.x;
    if (i < n) {
        int r = g_rowptr[i] + g_bsum[i >> 8];
        g_rowptr[i] = r;
        g_cursor[i] = r;
    }
    if (i == 0) g_rowptr[n] = e;
}
__global__ void k_fill(const int* __restrict__ src,
                       const int* __restrict__ dst, int e) {
    int i = blockIdx.x * blockDim.x + threadIdx.x;
    if (i < e) {
        int slot = atomicAdd(&g_cursor[dst[i]], 1);
        g_csr[slot] = src[i];
    }
}

// --------------------------- packed f32x2 helpers --------------------------
__device__ __forceinline__ unsigned long long pk2(float x) {
    unsigned long long r;
    asm("mov.b64 %0, {%1, %1};" : "=l"(r) : "f"(x));
    return r;
}
__device__ __forceinline__ void ffma2(unsigned long long& d,
                                      unsigned long long a,
                                      unsigned long long b) {
    asm("fma.rn.f32x2 %0, %1, %2, %0;" : "+l"(d) : "l"(a), "l"(b));
}
__device__ __forceinline__ float2 up2(unsigned long long v) {
    float2 r;
    asm("mov.b64 {%0, %1}, %2;" : "=f"(r.x), "=f"(r.y) : "l"(v));
    return r;
}

// --------------------------- GEMM ------------------------------------------
// 2 threads per node; thread computes 32 output cols (half = 0/1).
//   FIRST:  in' = raw input row
//   !FIRST: in' = relu(in_row * dis[node] + bias_prev)    (in = g_acc)
// Writes g_s only.
template<bool FIRST>
__global__ void __launch_bounds__(256)
k_gemm(const float* __restrict__ in, const float* __restrict__ W,
       const float* __restrict__ bias_prev, int n) {
    __shared__ ulonglong2 Ws2[64 * 16];        // row-major W, 16B granules
    __shared__ float bs[64];
    {
        const float4* W4 = reinterpret_cast<const float4*>(W);
        float4* S4 = reinterpret_cast<float4*>(Ws2);
#pragma unroll
        for (int i = threadIdx.x; i < 64 * 16; i += 256) S4[i] = W4[i];
        if (!FIRST && threadIdx.x < 64) bs[threadIdx.x] = bias_prev[threadIdx.x];
    }
    __syncthreads();

    int gid  = blockIdx.x * blockDim.x + threadIdx.x;
    int node = gid >> 1;
    int half = gid & 1;                        // cols [half*32, half*32+32)
    if (node >= n) return;

    float dn = g_dis[node];

    unsigned long long acc[16];
#pragma unroll
    for (int j = 0; j < 16; j++) acc[j] = 0ull;

    const float4* xr4 = reinterpret_cast<const float4*>(in + node * 64);

#pragma unroll 4
    for (int k4 = 0; k4 < 16; k4++) {
        float4 xv = __ldg(xr4 + k4);
        if (!FIRST) {
            xv.x = fmaxf(fmaf(xv.x, dn, bs[k4 * 4 + 0]), 0.0f);
            xv.y = fmaxf(fmaf(xv.y, dn, bs[k4 * 4 + 1]), 0.0f);
            xv.z = fmaxf(fmaf(xv.z, dn, bs[k4 * 4 + 2]), 0.0f);
            xv.w = fmaxf(fmaf(xv.w, dn, bs[k4 * 4 + 3]), 0.0f);
        }
        const float xs[4] = {xv.x, xv.y, xv.z, xv.w};
#pragma unroll
        for (int kk = 0; kk < 4; kk++) {
            int k = k4 * 4 + kk;
            unsigned long long xk2 = pk2(xs[kk]);
#pragma unroll
            for (int j = 0; j < 8; j++) {
                ulonglong2 w = Ws2[k * 16 + half * 8 + j];
                ffma2(acc[2 * j],     xk2, w.x);
                ffma2(acc[2 * j + 1], xk2, w.y);
            }
        }
    }

    float4* sp = reinterpret_cast<float4*>(g_s + node * 64 + half * 32);
#pragma unroll
    for (int j = 0; j < 8; j++) {
        float2 lo = up2(acc[2 * j]);
        float2 hi = up2(acc[2 * j + 1]);
        sp[j] = make_float4(lo.x * dn, lo.y * dn, hi.x * dn, hi.y * dn);
    }
}

// --------------------------- CSR gather ------------------------------------
// acc[v] = s[v] + sum_{j in rowptr[v]..rowptr[v+1]} s[csr[j]]
// 16 threads per node (one float4 column each). No atomics.
__global__ void __launch_bounds__(256)
k_gather(int n) {
    int idx  = blockIdx.x * blockDim.x + threadIdx.x;
    int node = idx >> 4;
    int c    = idx & 15;
    if (node >= n) return;

    int beg = __ldg(g_rowptr + node);
    int end = __ldg(g_rowptr + node + 1);

    const float4* s4 = reinterpret_cast<const float4*>(g_s);
    float4 a = s4[node * 16 + c];              // self loop
    for (int j = beg; j < end; j++) {
        int u = __ldg(g_csr + j);
        float4 v = __ldg(s4 + u * 16 + c);
        a.x += v.x; a.y += v.y; a.z += v.z; a.w += v.w;
    }
    reinterpret_cast<float4*>(g_acc)[node * 16 + c] = a;
}

// --------------------------- pool ------------------------------------------
// pool[g][f] = sum over nodes of relu(acc*dis + b2)
__global__ void k_pool(const int* __restrict__ gids,
                       const float* __restrict__ b2, int n) {
    int g = blockIdx.x;
    int lo = 0, hi = n;
    while (lo < hi) { int m = (lo + hi) >> 1; if (gids[m] < g) lo = m + 1; else hi = m; }
    int start = lo;
    lo = start; hi = n;
    while (lo < hi) { int m = (lo + hi) >> 1; if (gids[m] < g + 1) lo = m + 1; else hi = m; }
    int end = lo;

    int f = threadIdx.x & 63;
    int r = threadIdx.x >> 6;
    float bf = b2[f];
    float sum = 0.0f;
    for (int i = start + r; i < end; i += 4) {
        float d = g_dis[i];
        sum += fmaxf(fmaf(g_acc[i * 64 + f], d, bf), 0.0f);
    }
    __shared__ float red[4][64];
    red[r][f] = sum;
    __syncthreads();
    if (r == 0) g_pool[g * 64 + f] = red[0][f] + red[1][f] + red[2][f] + red[3][f];
}

// --------------------------- head MLP --------------------------------------
__global__ void k_head(const float* __restrict__ gfeat,
                       const float* __restrict__ gw, const float* __restrict__ gb,
                       const float* __restrict__ l1w, const float* __restrict__ l1b,
                       const float* __restrict__ l2w, const float* __restrict__ l2b,
                       const float* __restrict__ l3w, const float* __restrict__ l3b,
                       const float* __restrict__ l4w, const float* __restrict__ l4b,
                       float* __restrict__ out) {
    __shared__ float A[64][97];
    __shared__ float Bm[64][65];
    int t = threadIdx.x;

    for (int e = t; e < 64 * 64; e += 256) {          // z1
        int i = e >> 6, j = e & 63;
        float sum = l1b[j];
        for (int k = 0; k < 64; k++) sum = fmaf(g_pool[i * 64 + k], l1w[k * 64 + j], sum);
        A[i][j] = fmaxf(sum, 0.0f);
    }
    for (int e = t; e < 64 * 32; e += 256) {          // gx
        int i = e >> 5, j = e & 31;
        float sum = gb[j];
        for (int k = 0; k < 32; k++) sum = fmaf(gfeat[i * 32 + k], gw[k * 32 + j], sum);
        A[i][64 + j] = fmaxf(sum, 0.0f);
    }
    __syncthreads();
    for (int e = t; e < 64 * 64; e += 256) {          // z2
        int i = e >> 6, j = e & 63;
        float sum = l2b[j];
        for (int k = 0; k < 96; k++) sum = fmaf(A[i][k], l2w[k * 64 + j], sum);
        Bm[i][j] = fmaxf(sum, 0.0f);
    }
    __syncthreads();
    for (int e = t; e < 64 * 64; e += 256) {          // z3
        int i = e >> 6, j = e & 63;
        float sum = l3b[j];
        for (int k = 0; k < 64; k++) sum = fmaf(Bm[i][k], l3w[k * 64 + j], sum);
        A[i][j] = fmaxf(sum, 0.0f);
    }
    __syncthreads();
    if (t < 64) {
        float sum = l4b[0];
        for (int k = 0; k < 64; k++) sum = fmaf(A[t][k], l4w[k], sum);
        out[t] = sum;
    }
}

// ---------------------------------------------------------------------------
extern "C" void kernel_launch(void* const* d_in, const int* in_sizes, int n_in,
                              void* d_out, int out_size) {
    const float* x     = (const float*)d_in[0];
    const float* gfeat = (const float*)d_in[1];
    const float* cw[3] = {(const float*)d_in[2], (const float*)d_in[4], (const float*)d_in[6]};
    const float* cb[3] = {(const float*)d_in[3], (const float*)d_in[5], (const float*)d_in[7]};
    const float* l1w = (const float*)d_in[8];
    const float* l1b = (const float*)d_in[9];
    const float* gw  = (const float*)d_in[10];
    const float* gb  = (const float*)d_in[11];
    const float* l2w = (const float*)d_in[12];
    const float* l2b = (const float*)d_in[13];
    const float* l3w = (const float*)d_in[14];
    const float* l3b = (const float*)d_in[15];
    const float* l4w = (const float*)d_in[16];
    const float* l4b = (const float*)d_in[17];
    const int*   ei   = (const int*)d_in[18];
    const int*   gids = (const int*)d_in[19];
    float* out = (float*)d_out;

    int N = in_sizes[19];
    int E = in_sizes[18] / 2;
    const int* src = ei;
    const int* dst = ei + E;

    void* accp = nullptr;
    cudaGetSymbolAddress(&accp, g_acc);
    const float* acc_in = (const float*)accp;

    const int T = 256;
    int nb_n   = (N + T - 1) / T;              // 391
    int nb_e   = (E + T - 1) / T;
    int nb_2n  = (2 * N + T - 1) / T;          // gemm: 2 threads/node
    int nb_16n = (16 * N + T - 1) / T;         // gather: 16 threads/node

    // degree / dis / CSR build
    k_deg0 <<<nb_n, T>>>(N);
    k_degc <<<nb_e, T>>>(dst, E);
    k_dis  <<<nb_n, T>>>(N);
    k_scan1<<<nb_n, T>>>(N);
    k_scan2<<<1, 512>>>(nb_n);
    k_scan3<<<nb_n, T>>>(N, E);
    k_fill <<<nb_e, T>>>(src, dst, E);

    // layers
    k_gemm<true ><<<nb_2n, T>>>(x,      cw[0], nullptr, N);
    k_gather<<<nb_16n, T>>>(N);
    k_gemm<false><<<nb_2n, T>>>(acc_in, cw[1], cb[0], N);
    k_gather<<<nb_16n, T>>>(N);
    k_gemm<false><<<nb_2n, T>>>(acc_in, cw[2], cb[1], N);
    k_gather<<<nb_16n, T>>>(N);

    // pool + head
    k_pool<<<GG, T>>>(gids, cb[2], N);
    k_head<<<1, T>>>(gfeat, gw, gb, l1w, l1b, l2w, l2b, l3w, l3b, l4w, l4b, out);
}

// round 4
// speedup vs baseline: 2.1374x; 1.2359x over previous
#include <cuda_runtime.h>

// ---------------------------------------------------------------------------
// SimpleGCN, sm_100a. fp32; f32x2 GEMM (2 nodes/thread); CSR gather; fused
// activations. No atomics in the per-layer hot path.
// ---------------------------------------------------------------------------

#define NN 100000
#define EE 1600000
#define GG 64

__device__ float g_dis [NN];
__device__ int   g_degi[NN];
__device__ int   g_rowptr[NN + 1];
__device__ int   g_cursor[NN];
__device__ int   g_bsum[512];
__device__ int   g_csr[EE];
__device__ float g_s  [NN * 64];
__device__ float g_acc[NN * 64];
__device__ float g_pool[GG * 64];

// --------------------------- degree count ----------------------------------
__global__ void k_degc(const int* __restrict__ dst, int e) {
    int i = blockIdx.x * blockDim.x + threadIdx.x;
    if (i < e) atomicAdd(&g_degi[dst[i]], 1);
}

// --------------------------- scan (rowptr) + dis ---------------------------
__global__ void k_scan1(int n) {               // per-block scan of g_degi; dis
    __shared__ int s[256];
    int b = blockIdx.x, t = threadIdx.x;
    int i = b * 256 + t;
    int v = (i < n) ? g_degi[i] : 0;
    if (i < n) g_dis[i] = rsqrtf((float)v + 1.0f);
    s[t] = v;
    __syncthreads();
#pragma unroll
    for (int off = 1; off < 256; off <<= 1) {
        int add = (t >= off) ? s[t - off] : 0;
        __syncthreads();
        s[t] += add;
        __syncthreads();
    }
    if (i < n) g_rowptr[i] = s[t] - v;
    if (t == 255) g_bsum[b] = s[255];
}
__global__ void k_scan2(int nb) {
    __shared__ int s[512];
    int t = threadIdx.x;
    int v = (t < nb) ? g_bsum[t] : 0;
    s[t] = v;
    __syncthreads();
#pragma unroll
    for (int off = 1; off < 512; off <<= 1) {
        int add = (t >= off) ? s[t - off] : 0;
        __syncthreads();
        s[t] += add;
        __syncthreads();
    }
    if (t < nb) g_bsum[t] = s[t] - v;
}
__global__ void k_scan3(int n, int e) {
    int i = blockIdx.x * blockDim.x + threadIdx.x;
    if (i < n) {
        int r = g_rowptr[i] + g_bsum[i >> 8];
        g_rowptr[i] = r;
        g_cursor[i] = r;
    }
    if (i == 0) g_rowptr[n] = e;
}
__global__ void k_fill(const int* __restrict__ src,
                       const int* __restrict__ dst, int e) {
    int i = blockIdx.x * blockDim.x + threadIdx.x;
    if (i < e) {
        int slot = atomicAdd(&g_cursor[dst[i]], 1);
        g_csr[slot] = src[i];
    }
}

// --------------------------- packed f32x2 helpers --------------------------
__device__ __forceinline__ unsigned long long pk2(float x) {
    unsigned long long r;
    asm("mov.b64 %0, {%1, %1};" : "=l"(r) : "f"(x));
    return r;
}
__device__ __forceinline__ void ffma2(unsigned long long& d,
                                      unsigned long long a,
                                      unsigned long long b) {
    asm("fma.rn.f32x2 %0, %1, %2, %0;" : "+l"(d) : "l"(a), "l"(b));
}
__device__ __forceinline__ float2 up2(unsigned long long v) {
    float2 r;
    asm("mov.b64 {%0, %1}, %2;" : "=f"(r.x), "=f"(r.y) : "l"(v));
    return r;
}

// --------------------------- GEMM ------------------------------------------
// One thread = 2 nodes x 32 cols. Each 16B LDS of W feeds 4 FFMA2 (2 nodes).
//   FIRST:  in' = raw input row
//   !FIRST: in' = relu(in_row * dis + bias_prev)   (in = g_acc)
template<bool FIRST>
__global__ void __launch_bounds__(256)
k_gemm(const float* __restrict__ in, const float* __restrict__ W,
       const float* __restrict__ bias_prev, int n) {
    __shared__ ulonglong2 Ws2[64 * 16];        // row-major W, 16B granules
    __shared__ float bs[64];
    {
        const float4* W4 = reinterpret_cast<const float4*>(W);
        float4* S4 = reinterpret_cast<float4*>(Ws2);
#pragma unroll
        for (int i = threadIdx.x; i < 64 * 16; i += 256) S4[i] = W4[i];
        if (!FIRST && threadIdx.x < 64) bs[threadIdx.x] = bias_prev[threadIdx.x];
    }
    __syncthreads();

    int gid  = blockIdx.x * blockDim.x + threadIdx.x;
    int pair = gid >> 1;
    int half = gid & 1;                        // cols [half*32, half*32+32)
    int n0 = pair * 2;
    int n1 = n0 + 1;
    if (n0 >= n) return;
    bool has1 = (n1 < n);

    float d0 = g_dis[n0];
    float d1 = has1 ? g_dis[n1] : 0.0f;

    unsigned long long a0[16], a1[16];
#pragma unroll
    for (int j = 0; j < 16; j++) { a0[j] = 0ull; a1[j] = 0ull; }

    const float4* x0 = reinterpret_cast<const float4*>(in + (long)n0 * 64);
    const float4* x1 = reinterpret_cast<const float4*>(in + (long)n1 * 64);

#pragma unroll 4
    for (int k4 = 0; k4 < 16; k4++) {
        float4 v0 = __ldg(x0 + k4);
        float4 v1 = has1 ? __ldg(x1 + k4) : make_float4(0, 0, 0, 0);
        if (!FIRST) {
            float b0 = bs[k4 * 4 + 0], b1 = bs[k4 * 4 + 1];
            float b2 = bs[k4 * 4 + 2], b3 = bs[k4 * 4 + 3];
            v0.x = fmaxf(fmaf(v0.x, d0, b0), 0.0f);
            v0.y = fmaxf(fmaf(v0.y, d0, b1), 0.0f);
            v0.z = fmaxf(fmaf(v0.z, d0, b2), 0.0f);
            v0.w = fmaxf(fmaf(v0.w, d0, b3), 0.0f);
            v1.x = fmaxf(fmaf(v1.x, d1, b0), 0.0f);
            v1.y = fmaxf(fmaf(v1.y, d1, b1), 0.0f);
            v1.z = fmaxf(fmaf(v1.z, d1, b2), 0.0f);
            v1.w = fmaxf(fmaf(v1.w, d1, b3), 0.0f);
        }
        const float xs0[4] = {v0.x, v0.y, v0.z, v0.w};
        const float xs1[4] = {v1.x, v1.y, v1.z, v1.w};
#pragma unroll
        for (int kk = 0; kk < 4; kk++) {
            int k = k4 * 4 + kk;
            unsigned long long p0 = pk2(xs0[kk]);
            unsigned long long p1 = pk2(xs1[kk]);
#pragma unroll
            for (int j = 0; j < 8; j++) {
                ulonglong2 w = Ws2[k * 16 + half * 8 + j];
                ffma2(a0[2 * j],     p0, w.x);
                ffma2(a0[2 * j + 1], p0, w.y);
                ffma2(a1[2 * j],     p1, w.x);
                ffma2(a1[2 * j + 1], p1, w.y);
            }
        }
    }

    float4* sp0 = reinterpret_cast<float4*>(g_s + (long)n0 * 64 + half * 32);
#pragma unroll
    for (int j = 0; j < 8; j++) {
        float2 lo = up2(a0[2 * j]);
        float2 hi = up2(a0[2 * j + 1]);
        sp0[j] = make_float4(lo.x * d0, lo.y * d0, hi.x * d0, hi.y * d0);
    }
    if (has1) {
        float4* sp1 = reinterpret_cast<float4*>(g_s + (long)n1 * 64 + half * 32);
#pragma unroll
        for (int j = 0; j < 8; j++) {
            float2 lo = up2(a1[2 * j]);
            float2 hi = up2(a1[2 * j + 1]);
            sp1[j] = make_float4(lo.x * d1, lo.y * d1, hi.x * d1, hi.y * d1);
        }
    }
}

// --------------------------- CSR gather ------------------------------------
// acc[v] = s[v] + sum_{in-edges} s[u].  16 threads/node, unroll-4 prefetch.
__global__ void __launch_bounds__(256)
k_gather(int n) {
    int idx  = blockIdx.x * blockDim.x + threadIdx.x;
    int node = idx >> 4;
    int c    = idx & 15;
    if (node >= n) return;

    int beg = __ldg(g_rowptr + node);
    int end = __ldg(g_rowptr + node + 1);

    const float4* s4 = reinterpret_cast<const float4*>(g_s);
    float4 a = s4[(long)node * 16 + c];        // self loop
    int j = beg;
    for (; j + 4 <= end; j += 4) {
        int u0 = __ldg(g_csr + j);
        int u1 = __ldg(g_csr + j + 1);
        int u2 = __ldg(g_csr + j + 2);
        int u3 = __ldg(g_csr + j + 3);
        float4 v0 = __ldg(s4 + (long)u0 * 16 + c);
        float4 v1 = __ldg(s4 + (long)u1 * 16 + c);
        float4 v2 = __ldg(s4 + (long)u2 * 16 + c);
        float4 v3 = __ldg(s4 + (long)u3 * 16 + c);
        a.x += v0.x + v1.x + v2.x + v3.x;
        a.y += v0.y + v1.y + v2.y + v3.y;
        a.z += v0.z + v1.z + v2.z + v3.z;
        a.w += v0.w + v1.w + v2.w + v3.w;
    }
    for (; j < end; j++) {
        int u = __ldg(g_csr + j);
        float4 v = __ldg(s4 + (long)u * 16 + c);
        a.x += v.x; a.y += v.y; a.z += v.z; a.w += v.w;
    }
    reinterpret_cast<float4*>(g_acc)[(long)node * 16 + c] = a;
}

// --------------------------- pool (node-parallel) --------------------------
// Each thread: feature f, node stride 4 within a 256-node block slice.
// Running (gid,sum); flush with atomicAdd on transitions (ids sorted).
__global__ void __launch_bounds__(256)
k_pool(const int* __restrict__ gids, const float* __restrict__ b2, int n) {
    int t = threadIdx.x;
    int f = t & 63;
    int r = t >> 6;
    int base = blockIdx.x * 256;
    float bf = __ldg(b2 + f);

    int cur = -1;
    float sum = 0.0f;
    for (int i = base + r; i < base + 256 && i < n; i += 4) {
        int g = __ldg(gids + i);
        float d = g_dis[i];
        float v = fmaxf(fmaf(g_acc[(long)i * 64 + f], d, bf), 0.0f);
        if (g != cur) {
            if (cur >= 0) atomicAdd(&g_pool[cur * 64 + f], sum);
            cur = g;
            sum = v;
        } else {
            sum += v;
        }
    }
    if (cur >= 0) atomicAdd(&g_pool[cur * 64 + f], sum);
}

// --------------------------- head MLP --------------------------------------
__global__ void k_head(const float* __restrict__ gfeat,
                       const float* __restrict__ gw, const float* __restrict__ gb,
                       const float* __restrict__ l1w, const float* __restrict__ l1b,
                       const float* __restrict__ l2w, const float* __restrict__ l2b,
                       const float* __restrict__ l3w, const float* __restrict__ l3b,
                       const float* __restrict__ l4w, const float* __restrict__ l4b,
                       float* __restrict__ out) {
    __shared__ float A[64][97];
    __shared__ float Bm[64][65];
    int t = threadIdx.x;

    for (int e = t; e < 64 * 64; e += 256) {          // z1
        int i = e >> 6, j = e & 63;
        float sum = l1b[j];
        for (int k = 0; k < 64; k++) sum = fmaf(g_pool[i * 64 + k], l1w[k * 64 + j], sum);
        A[i][j] = fmaxf(sum, 0.0f);
    }
    for (int e = t; e < 64 * 32; e += 256) {          // gx
        int i = e >> 5, j = e & 31;
        float sum = gb[j];
        for (int k = 0; k < 32; k++) sum = fmaf(gfeat[i * 32 + k], gw[k * 32 + j], sum);
        A[i][64 + j] = fmaxf(sum, 0.0f);
    }
    __syncthreads();
    for (int e = t; e < 64 * 64; e += 256) {          // z2
        int i = e >> 6, j = e & 63;
        float sum = l2b[j];
        for (int k = 0; k < 96; k++) sum = fmaf(A[i][k], l2w[k * 64 + j], sum);
        Bm[i][j] = fmaxf(sum, 0.0f);
    }
    __syncthreads();
    for (int e = t; e < 64 * 64; e += 256) {          // z3
        int i = e >> 6, j = e & 63;
        float sum = l3b[j];
        for (int k = 0; k < 64; k++) sum = fmaf(Bm[i][k], l3w[k * 64 + j], sum);
        A[i][j] = fmaxf(sum, 0.0f);
    }
    __syncthreads();
    if (t < 64) {
        float sum = l4b[0];
        for (int k = 0; k < 64; k++) sum = fmaf(A[t][k], l4w[k], sum);
        out[t] = sum;
    }
}

// ---------------------------------------------------------------------------
extern "C" void kernel_launch(void* const* d_in, const int* in_sizes, int n_in,
                              void* d_out, int out_size) {
    const float* x     = (const float*)d_in[0];
    const float* gfeat = (const float*)d_in[1];
    const float* cw[3] = {(const float*)d_in[2], (const float*)d_in[4], (const float*)d_in[6]};
    const float* cb[3] = {(const float*)d_in[3], (const float*)d_in[5], (const float*)d_in[7]};
    const float* l1w = (const float*)d_in[8];
    const float* l1b = (const float*)d_in[9];
    const float* gw  = (const float*)d_in[10];
    const float* gb  = (const float*)d_in[11];
    const float* l2w = (const float*)d_in[12];
    const float* l2b = (const float*)d_in[13];
    const float* l3w = (const float*)d_in[14];
    const float* l3b = (const float*)d_in[15];
    const float* l4w = (const float*)d_in[16];
    const float* l4b = (const float*)d_in[17];
    const int*   ei   = (const int*)d_in[18];
    const int*   gids = (const int*)d_in[19];
    float* out = (float*)d_out;

    int N = in_sizes[19];
    int E = in_sizes[18] / 2;
    const int* src = ei;
    const int* dst = ei + E;

    void *accp = nullptr, *degp = nullptr, *poolp = nullptr;
    cudaGetSymbolAddress(&accp, g_acc);
    cudaGetSymbolAddress(&degp, g_degi);
    cudaGetSymbolAddress(&poolp, g_pool);
    const float* acc_in = (const float*)accp;

    const int T = 256;
    int nb_n   = (N + T - 1) / T;
    int nb_e   = (E + T - 1) / T;
    int nb_16n = (16 * N + T - 1) / T;

    // degree / dis / CSR build
    cudaMemsetAsync(degp, 0, (size_t)N * sizeof(int));
    cudaMemsetAsync(poolp, 0, (size_t)GG * 64 * sizeof(float));
    k_degc <<<nb_e, T>>>(dst, E);
    k_scan1<<<nb_n, T>>>(N);
    k_scan2<<<1, 512>>>(nb_n);
    k_scan3<<<nb_n, T>>>(N, E);
    k_fill <<<nb_e, T>>>(src, dst, E);

    // layers (gemm: 1 thread per node-pair-half -> N threads total)
    k_gemm<true ><<<nb_n, T>>>(x,      cw[0], nullptr, N);
    k_gather<<<nb_16n, T>>>(N);
    k_gemm<false><<<nb_n, T>>>(acc_in, cw[1], cb[0], N);
    k_gather<<<nb_16n, T>>>(N);
    k_gemm<false><<<nb_n, T>>>(acc_in, cw[2], cb[1], N);
    k_gather<<<nb_16n, T>>>(N);

    // pool + head
    k_pool<<<nb_n, T>>>(gids, cb[2], N);
    k_head<<<1, T>>>(gfeat, gw, gb, l1w, l1b, l2w, l2b, l3w, l3b, l4w, l4b, out);
}

// round 6
// speedup vs baseline: 2.2658x; 1.0601x over previous
#include <cuda_runtime.h>
#include <cuda_fp16.h>

// ---------------------------------------------------------------------------
// SimpleGCN, sm_100a. fp32 compute; fp16 message rows (g_s) to halve the
// L2 traffic of the edge gather. CSR gather, no hot-path atomics.
//
//   s[n]   = fp16( (in' @ W)[n] * dis[n] )          (GEMM, writes g_s fp16)
//   acc[v] = s[v] + sum_{in-edges} s[u]             (fp32 accumulate)
//   in'    = relu(acc * dis + b_prev)               (fused into next GEMM/pool)
// ---------------------------------------------------------------------------

#define NN 100000
#define EE 1600000
#define GG 64

__device__ float  g_dis [NN];
__device__ int    g_degi[NN];
__device__ int    g_rowptr[NN + 1];
__device__ int    g_cursor[NN];
__device__ int    g_bsum[512];
__device__ int    g_csr[EE];
__device__ __half g_s  [NN * 64];     // fp16 message rows, 128 B each
__device__ float  g_acc[NN * 64];
__device__ float  g_pool[GG * 64];

// --------------------------- degree count ----------------------------------
__global__ void k_degc(const int* __restrict__ dst, int e) {
    int i = blockIdx.x * blockDim.x + threadIdx.x;
    if (i < e) atomicAdd(&g_degi[dst[i]], 1);
}

// --------------------------- scan (rowptr) + dis ---------------------------
__global__ void k_scan1(int n) {
    __shared__ int s[256];
    int b = blockIdx.x, t = threadIdx.x;
    int i = b * 256 + t;
    int v = (i < n) ? g_degi[i] : 0;
    if (i < n) g_dis[i] = rsqrtf((float)v + 1.0f);
    s[t] = v;
    __syncthreads();
#pragma unroll
    for (int off = 1; off < 256; off <<= 1) {
        int add = (t >= off) ? s[t - off] : 0;
        __syncthreads();
        s[t] += add;
        __syncthreads();
    }
    if (i < n) g_rowptr[i] = s[t] - v;
    if (t == 255) g_bsum[b] = s[255];
}
__global__ void k_scan2(int nb) {
    __shared__ int s[512];
    int t = threadIdx.x;
    int v = (t < nb) ? g_bsum[t] : 0;
    s[t] = v;
    __syncthreads();
#pragma unroll
    for (int off = 1; off < 512; off <<= 1) {
        int add = (t >= off) ? s[t - off] : 0;
        __syncthreads();
        s[t] += add;
        __syncthreads();
    }
    if (t < nb) g_bsum[t] = s[t] - v;
}
__global__ void k_scan3(int n, int e) {
    int i = blockIdx.x * blockDim.x + threadIdx.x;
    if (i < n) {
        int r = g_rowptr[i] + g_bsum[i >> 8];
        g_rowptr[i] = r;
        g_cursor[i] = r;
    }
    if (i == 0) g_rowptr[n] = e;
}
__global__ void k_fill(const int* __restrict__ src,
                       const int* __restrict__ dst, int e) {
    int i = blockIdx.x * blockDim.x + threadIdx.x;
    if (i < e) {
        int slot = atomicAdd(&g_cursor[dst[i]], 1);
        g_csr[slot] = src[i];
    }
}

// --------------------------- packed f32x2 helpers --------------------------
__device__ __forceinline__ unsigned long long pk2(float x) {
    unsigned long long r;
    asm("mov.b64 %0, {%1, %1};" : "=l"(r) : "f"(x));
    return r;
}
__device__ __forceinline__ void ffma2(unsigned long long& d,
                                      unsigned long long a,
                                      unsigned long long b) {
    asm("fma.rn.f32x2 %0, %1, %2, %0;" : "+l"(d) : "l"(a), "l"(b));
}
__device__ __forceinline__ float2 up2(unsigned long long v) {
    float2 r;
    asm("mov.b64 {%0, %1}, %2;" : "=f"(r.x), "=f"(r.y) : "l"(v));
    return r;
}

// --------------------------- GEMM ------------------------------------------
// One thread = 2 nodes x 32 cols (each 16B LDS of W feeds 4 FFMA2).
// Epilogue: scale by dis and store fp16 to g_s.
template<bool FIRST>
__global__ void __launch_bounds__(256)
k_gemm(const float* __restrict__ in, const float* __restrict__ W,
       const float* __restrict__ bias_prev, int n) {
    __shared__ ulonglong2 Ws2[64 * 16];
    __shared__ float bs[64];
    {
        const float4* W4 = reinterpret_cast<const float4*>(W);
        float4* S4 = reinterpret_cast<float4*>(Ws2);
#pragma unroll
        for (int i = threadIdx.x; i < 64 * 16; i += 256) S4[i] = W4[i];
        if (!FIRST && threadIdx.x < 64) bs[threadIdx.x] = bias_prev[threadIdx.x];
    }
    __syncthreads();

    int gid  = blockIdx.x * blockDim.x + threadIdx.x;
    int pair = gid >> 1;
    int half = gid & 1;
    int n0 = pair * 2;
    int n1 = n0 + 1;
    if (n0 >= n) return;
    bool has1 = (n1 < n);

    float d0 = g_dis[n0];
    float d1 = has1 ? g_dis[n1] : 0.0f;

    unsigned long long a0[16], a1[16];
#pragma unroll
    for (int j = 0; j < 16; j++) { a0[j] = 0ull; a1[j] = 0ull; }

    const float4* x0 = reinterpret_cast<const float4*>(in + (long)n0 * 64);
    const float4* x1 = reinterpret_cast<const float4*>(in + (long)n1 * 64);

#pragma unroll 4
    for (int k4 = 0; k4 < 16; k4++) {
        float4 v0 = __ldg(x0 + k4);
        float4 v1 = has1 ? __ldg(x1 + k4) : make_float4(0, 0, 0, 0);
        if (!FIRST) {
            float b0 = bs[k4 * 4 + 0], b1 = bs[k4 * 4 + 1];
            float b2 = bs[k4 * 4 + 2], b3 = bs[k4 * 4 + 3];
            v0.x = fmaxf(fmaf(v0.x, d0, b0), 0.0f);
            v0.y = fmaxf(fmaf(v0.y, d0, b1), 0.0f);
            v0.z = fmaxf(fmaf(v0.z, d0, b2), 0.0f);
            v0.w = fmaxf(fmaf(v0.w, d0, b3), 0.0f);
            v1.x = fmaxf(fmaf(v1.x, d1, b0), 0.0f);
            v1.y = fmaxf(fmaf(v1.y, d1, b1), 0.0f);
            v1.z = fmaxf(fmaf(v1.z, d1, b2), 0.0f);
            v1.w = fmaxf(fmaf(v1.w, d1, b3), 0.0f);
        }
        const float xs0[4] = {v0.x, v0.y, v0.z, v0.w};
        const float xs1[4] = {v1.x, v1.y, v1.z, v1.w};
#pragma unroll
        for (int kk = 0; kk < 4; kk++) {
            int k = k4 * 4 + kk;
            unsigned long long p0 = pk2(xs0[kk]);
            unsigned long long p1 = pk2(xs1[kk]);
#pragma unroll
            for (int j = 0; j < 8; j++) {
                ulonglong2 w = Ws2[k * 16 + half * 8 + j];
                ffma2(a0[2 * j],     p0, w.x);
                ffma2(a0[2 * j + 1], p0, w.y);
                ffma2(a1[2 * j],     p1, w.x);
                ffma2(a1[2 * j + 1], p1, w.y);
            }
        }
    }

    // epilogue: *dis, convert to fp16, store 32 cols
    __half2* sp0 = reinterpret_cast<__half2*>(g_s + (long)n0 * 64 + half * 32);
#pragma unroll
    for (int j = 0; j < 16; j++) {
        float2 v = up2(a0[j]);
        v.x *= d0; v.y *= d0;
        sp0[j] = __float22half2_rn(v);
    }
    if (has1) {
        __half2* sp1 = reinterpret_cast<__half2*>(g_s + (long)n1 * 64 + half * 32);
#pragma unroll
        for (int j = 0; j < 16; j++) {
            float2 v = up2(a1[j]);
            v.x *= d1; v.y *= d1;
            sp1[j] = __float22half2_rn(v);
        }
    }
}

// --------------------------- CSR gather ------------------------------------
// acc[v] = s[v] + sum s[u], fp16 rows, fp32 accumulate.
// 8 threads/node; each handles 8 halves (one uint4).
__device__ __forceinline__ void acc8(float2* a, uint4 p) {
    const __half2* h = reinterpret_cast<const __half2*>(&p);
#pragma unroll
    for (int q = 0; q < 4; q++) {
        float2 f = __half22float2(h[q]);
        a[q].x += f.x;
        a[q].y += f.y;
    }
}
__global__ void __launch_bounds__(256)
k_gather(int n) {
    int idx  = blockIdx.x * blockDim.x + threadIdx.x;
    int node = idx >> 3;
    int c    = idx & 7;
    if (node >= n) return;

    int beg = __ldg(g_rowptr + node);
    int end = __ldg(g_rowptr + node + 1);

    const uint4* s8 = reinterpret_cast<const uint4*>(g_s);
    float2 a[4] = {{0,0},{0,0},{0,0},{0,0}};
    acc8(a, s8[(long)node * 8 + c]);           // self loop

    int j = beg;
    for (; j + 4 <= end; j += 4) {
        int u0 = __ldg(g_csr + j);
        int u1 = __ldg(g_csr + j + 1);
        int u2 = __ldg(g_csr + j + 2);
        int u3 = __ldg(g_csr + j + 3);
        uint4 p0 = __ldg(s8 + (long)u0 * 8 + c);
        uint4 p1 = __ldg(s8 + (long)u1 * 8 + c);
        uint4 p2 = __ldg(s8 + (long)u2 * 8 + c);
        uint4 p3 = __ldg(s8 + (long)u3 * 8 + c);
        acc8(a, p0); acc8(a, p1); acc8(a, p2); acc8(a, p3);
    }
    for (; j < end; j++) {
        int u = __ldg(g_csr + j);
        acc8(a, __ldg(s8 + (long)u * 8 + c));
    }

    float4* op = reinterpret_cast<float4*>(g_acc + (long)node * 64 + c * 8);
    op[0] = make_float4(a[0].x, a[0].y, a[1].x, a[1].y);
    op[1] = make_float4(a[2].x, a[2].y, a[3].x, a[3].y);
}

// --------------------------- pool (node-parallel) --------------------------
__global__ void __launch_bounds__(256)
k_pool(const int* __restrict__ gids, const float* __restrict__ b2, int n) {
    int t = threadIdx.x;
    int f = t & 63;
    int r = t >> 6;
    int base = blockIdx.x * 256;
    int lim = base + 256 < n ? base + 256 : n;
    float bf = __ldg(b2 + f);

    int cur = -1;
    float sum = 0.0f;
    for (int i = base + r; i < lim; i += 4) {
        int g = __ldg(gids + i);
        float d = g_dis[i];
        float v = fmaxf(fmaf(g_acc[(long)i * 64 + f], d, bf), 0.0f);
        if (g != cur) {
            if (cur >= 0) atomicAdd(&g_pool[cur * 64 + f], sum);
            cur = g;
            sum = v;
        } else {
            sum += v;
        }
    }
    if (cur >= 0) atomicAdd(&g_pool[cur * 64 + f], sum);
}

// --------------------------- head MLP --------------------------------------
__global__ void k_head(const float* __restrict__ gfeat,
                       const float* __restrict__ gw, const float* __restrict__ gb,
                       const float* __restrict__ l1w, const float* __restrict__ l1b,
                       const float* __restrict__ l2w, const float* __restrict__ l2b,
                       const float* __restrict__ l3w, const float* __restrict__ l3b,
                       const float* __restrict__ l4w, const float* __restrict__ l4b,
                       float* __restrict__ out) {
    __shared__ float A[64][97];
    __shared__ float Bm[64][65];
    int t = threadIdx.x;

    for (int e = t; e < 64 * 64; e += 256) {          // z1
        int i = e >> 6, j = e & 63;
        float sum = l1b[j];
        for (int k = 0; k < 64; k++) sum = fmaf(g_pool[i * 64 + k], __ldg(l1w + k * 64 + j), sum);
        A[i][j] = fmaxf(sum, 0.0f);
    }
    for (int e = t; e < 64 * 32; e += 256) {          // gx
        int i = e >> 5, j = e & 31;
        float sum = gb[j];
        for (int k = 0; k < 32; k++) sum = fmaf(__ldg(gfeat + i * 32 + k), __ldg(gw + k * 32 + j), sum);
        A[i][64 + j] = fmaxf(sum, 0.0f);
    }
    __syncthreads();
    for (int e = t; e < 64 * 64; e += 256) {          // z2
        int i = e >> 6, j = e & 63;
        float sum = l2b[j];
        for (int k = 0; k < 96; k++) sum = fmaf(A[i][k], __ldg(l2w + k * 64 + j), sum);
        Bm[i][j] = fmaxf(sum, 0.0f);
    }
    __syncthreads();
    for (int e = t; e < 64 * 64; e += 256) {          // z3
        int i = e >> 6, j = e & 63;
        float sum = l3b[j];
        for (int k = 0; k < 64; k++) sum = fmaf(Bm[i][k], __ldg(l3w + k * 64 + j), sum);
        A[i][j] = fmaxf(sum, 0.0f);
    }
    __syncthreads();
    if (t < 64) {
        float sum = l4b[0];
        for (int k = 0; k < 64; k++) sum = fmaf(A[t][k], __ldg(l4w + k), sum);
        out[t] = sum;
    }
}

// ---------------------------------------------------------------------------
extern "C" void kernel_launch(void* const* d_in, const int* in_sizes, int n_in,
                              void* d_out, int out_size) {
    const float* x     = (const float*)d_in[0];
    const float* gfeat = (const float*)d_in[1];
    const float* cw[3] = {(const float*)d_in[2], (const float*)d_in[4], (const float*)d_in[6]};
    const float* cb[3] = {(const float*)d_in[3], (const float*)d_in[5], (const float*)d_in[7]};
    const float* l1w = (const float*)d_in[8];
    const float* l1b = (const float*)d_in[9];
    const float* gw  = (const float*)d_in[10];
    const float* gb  = (const float*)d_in[11];
    const float* l2w = (const float*)d_in[12];
    const float* l2b = (const float*)d_in[13];
    const float* l3w = (const float*)d_in[14];
    const float* l3b = (const float*)d_in[15];
    const float* l4w = (const float*)d_in[16];
    const float* l4b = (const float*)d_in[17];
    const int*   ei   = (const int*)d_in[18];
    const int*   gids = (const int*)d_in[19];
    float* out = (float*)d_out;

    int N = in_sizes[19];
    int E = in_sizes[18] / 2;
    const int* src = ei;
    const int* dst = ei + E;

    void *accp = nullptr, *degp = nullptr, *poolp = nullptr;
    cudaGetSymbolAddress(&accp, g_acc);
    cudaGetSymbolAddress(&degp, g_degi);
    cudaGetSymbolAddress(&poolp, g_pool);
    const float* acc_in = (const float*)accp;

    const int T = 256;
    int nb_n  = (N + T - 1) / T;
    int nb_e  = (E + T - 1) / T;
    int nb_8n = (8 * N + T - 1) / T;

    // degree / dis / CSR build
    cudaMemsetAsync(degp, 0, (size_t)N * sizeof(int));
    cudaMemsetAsync(poolp, 0, (size_t)GG * 64 * sizeof(float));
    k_degc <<<nb_e, T>>>(dst, E);
    k_scan1<<<nb_n, T>>>(N);
    k_scan2<<<1, 512>>>(nb_n);
    k_scan3<<<nb_n, T>>>(N, E);
    k_fill <<<nb_e, T>>>(src, dst, E);

    // layers
    k_gemm<true ><<<nb_n, T>>>(x,      cw[0], nullptr, N);
    k_gather<<<nb_8n, T>>>(N);
    k_gemm<false><<<nb_n, T>>>(acc_in, cw[1], cb[0], N);
    k_gather<<<nb_8n, T>>>(N);
    k_gemm<false><<<nb_n, T>>>(acc_in, cw[2], cb[1], N);
    k_gather<<<nb_8n, T>>>(N);

    // pool + head
    k_pool<<<nb_n, T>>>(gids, cb[2], N);
    k_head<<<1, T>>>(gfeat, gw, gb, l1w, l1b, l2w, l2b, l3w, l3b, l4w, l4b, out);
}

// round 7
// speedup vs baseline: 2.3601x; 1.0416x over previous
#include <cuda_runtime.h>
#include <cuda_fp16.h>

// ---------------------------------------------------------------------------
// SimpleGCN, sm_100a. fp32 compute, fp16 messages AND activations.
//   s[n] = fp16( (h_in @ W)[n] * dis[n] )            k_gemm   (g_h/x -> g_s)
//   h[v] = fp16( relu( (s[v]+sum s[u]) * dis + b ) ) k_gather (g_s -> g_h)
// CSR gather (no hot-path atomics). gemm0 overlapped with CSR build via
// stream fork/join (graph-capture safe event pattern).
// ---------------------------------------------------------------------------

#define NN 100000
#define EE 1600000
#define GG 64

__device__ float  g_dis [NN];
__device__ int    g_degi[NN];
__device__ int    g_rowptr[NN + 1];
__device__ int    g_cursor[NN];
__device__ int    g_bsum[512];
__device__ int    g_csr[EE];
__device__ __half g_s [NN * 64];      // fp16 message rows (gemm out)
__device__ __half g_h [NN * 64];      // fp16 activations   (gather out)
__device__ float  g_pool[GG * 64];

// --------------------------- zero (degi + pool) ----------------------------
__global__ void k_zero(int n) {
    int i = blockIdx.x * blockDim.x + threadIdx.x;
    if (i < n) g_degi[i] = 0;
    if (i < GG * 64) g_pool[i] = 0.0f;
}

// --------------------------- degree count (4 edges/thread) -----------------
__global__ void k_degc(const int* __restrict__ dst, int e) {
    int i = (blockIdx.x * blockDim.x + threadIdx.x) * 4;
    if (i + 3 < e) {
        int4 d = *reinterpret_cast<const int4*>(dst + i);
        atomicAdd(&g_degi[d.x], 1);
        atomicAdd(&g_degi[d.y], 1);
        atomicAdd(&g_degi[d.z], 1);
        atomicAdd(&g_degi[d.w], 1);
    } else {
        for (; i < e; i++) atomicAdd(&g_degi[dst[i]], 1);
    }
}

// --------------------------- scan1: block-local scan + dis -----------------
__global__ void k_scan1(int n) {
    __shared__ int s[256];
    int b = blockIdx.x, t = threadIdx.x;
    int i = b * 256 + t;
    int v = (i < n) ? g_degi[i] : 0;
    if (i < n) g_dis[i] = rsqrtf((float)v + 1.0f);
    s[t] = v;
    __syncthreads();
#pragma unroll
    for (int off = 1; off < 256; off <<= 1) {
        int add = (t >= off) ? s[t - off] : 0;
        __syncthreads();
        s[t] += add;
        __syncthreads();
    }
    if (i < n) g_rowptr[i] = s[t] - v;         // exclusive within block
    if (t == 255) g_bsum[b] = s[255];          // raw block total
}

// --------------------------- scan2+3 fused: offsets + cursor ---------------
__global__ void k_scan3(int n, int e) {
    __shared__ int sh[256];
    int b = blockIdx.x, t = threadIdx.x;
    int acc = 0;
    for (int j = t; j < b; j += 256) acc += g_bsum[j];
    sh[t] = acc;
    __syncthreads();
#pragma unroll
    for (int off = 128; off > 0; off >>= 1) {
        if (t < off) sh[t] += sh[t + off];
        __syncthreads();
    }
    int offset = sh[0];
    int i = b * 256 + t;
    if (i < n) {
        int r = g_rowptr[i] + offset;
        g_rowptr[i] = r;
        g_cursor[i] = r;
    }
    if (b == 0 && t == 0) g_rowptr[n] = e;
}

__global__ void k_fill(const int* __restrict__ src,
                       const int* __restrict__ dst, int e) {
    int i = blockIdx.x * blockDim.x + threadIdx.x;
    if (i < e) {
        int slot = atomicAdd(&g_cursor[dst[i]], 1);
        g_csr[slot] = src[i];
    }
}

// --------------------------- packed f32x2 helpers --------------------------
__device__ __forceinline__ unsigned long long pk2(float x) {
    unsigned long long r;
    asm("mov.b64 %0, {%1, %1};" : "=l"(r) : "f"(x));
    return r;
}
__device__ __forceinline__ void ffma2(unsigned long long& d,
                                      unsigned long long a,
                                      unsigned long long b) {
    asm("fma.rn.f32x2 %0, %1, %2, %0;" : "+l"(d) : "l"(a), "l"(b));
}
__device__ __forceinline__ float2 up2(unsigned long long v) {
    float2 r;
    asm("mov.b64 {%0, %1}, %2;" : "=f"(r.x), "=f"(r.y) : "l"(v));
    return r;
}

// --------------------------- GEMM ------------------------------------------
// One thread = 2 nodes x 32 cols. FIRST: fp32 raw x input. !FIRST: fp16 g_h.
// Epilogue: * dis, store fp16 to g_s. No bias/relu (done in gather).
template<bool FIRST>
__global__ void __launch_bounds__(256)
k_gemm(const float* __restrict__ in, const __half* __restrict__ in_h,
       const float* __restrict__ W, int n) {
    __shared__ ulonglong2 Ws2[64 * 16];
    {
        const float4* W4 = reinterpret_cast<const float4*>(W);
        float4* S4 = reinterpret_cast<float4*>(Ws2);
#pragma unroll
        for (int i = threadIdx.x; i < 64 * 16; i += 256) S4[i] = W4[i];
    }
    __syncthreads();

    int gid  = blockIdx.x * blockDim.x + threadIdx.x;
    int pair = gid >> 1;
    int half = gid & 1;
    int n0 = pair * 2;
    int n1 = n0 + 1;
    if (n0 >= n) return;
    bool has1 = (n1 < n);

    float d0 = g_dis[n0];
    float d1 = has1 ? g_dis[n1] : 0.0f;

    unsigned long long a0[16], a1[16];
#pragma unroll
    for (int j = 0; j < 16; j++) { a0[j] = 0ull; a1[j] = 0ull; }

    if (FIRST) {
        const float4* x0 = reinterpret_cast<const float4*>(in + (long)n0 * 64);
        const float4* x1 = reinterpret_cast<const float4*>(in + (long)n1 * 64);
#pragma unroll 4
        for (int k4 = 0; k4 < 16; k4++) {
            float4 v0 = __ldg(x0 + k4);
            float4 v1 = has1 ? __ldg(x1 + k4) : make_float4(0, 0, 0, 0);
            const float xs0[4] = {v0.x, v0.y, v0.z, v0.w};
            const float xs1[4] = {v1.x, v1.y, v1.z, v1.w};
#pragma unroll
            for (int kk = 0; kk < 4; kk++) {
                int k = k4 * 4 + kk;
                unsigned long long p0 = pk2(xs0[kk]);
                unsigned long long p1 = pk2(xs1[kk]);
#pragma unroll
                for (int j = 0; j < 8; j++) {
                    ulonglong2 w = Ws2[k * 16 + half * 8 + j];
                    ffma2(a0[2 * j],     p0, w.x);
                    ffma2(a0[2 * j + 1], p0, w.y);
                    ffma2(a1[2 * j],     p1, w.x);
                    ffma2(a1[2 * j + 1], p1, w.y);
                }
            }
        }
    } else {
        const uint4* x0 = reinterpret_cast<const uint4*>(in_h + (long)n0 * 64);
        const uint4* x1 = reinterpret_cast<const uint4*>(in_h + (long)n1 * 64);
#pragma unroll 2
        for (int k8 = 0; k8 < 8; k8++) {
            uint4 q0 = __ldg(x0 + k8);
            uint4 q1 = has1 ? __ldg(x1 + k8) : make_uint4(0, 0, 0, 0);
            const __half2* h0 = reinterpret_cast<const __half2*>(&q0);
            const __half2* h1 = reinterpret_cast<const __half2*>(&q1);
#pragma unroll
            for (int kk = 0; kk < 4; kk++) {
                float2 f0 = __half22float2(h0[kk]);
                float2 f1 = __half22float2(h1[kk]);
                int k = k8 * 8 + kk * 2;
#pragma unroll
                for (int s = 0; s < 2; s++) {
                    float u0 = s ? f0.y : f0.x;
                    float u1 = s ? f1.y : f1.x;
                    unsigned long long p0 = pk2(u0);
                    unsigned long long p1 = pk2(u1);
#pragma unroll
                    for (int j = 0; j < 8; j++) {
                        ulonglong2 w = Ws2[(k + s) * 16 + half * 8 + j];
                        ffma2(a0[2 * j],     p0, w.x);
                        ffma2(a0[2 * j + 1], p0, w.y);
                        ffma2(a1[2 * j],     p1, w.x);
                        ffma2(a1[2 * j + 1], p1, w.y);
                    }
                }
            }
        }
    }

    __half2* sp0 = reinterpret_cast<__half2*>(g_s + (long)n0 * 64 + half * 32);
#pragma unroll
    for (int j = 0; j < 16; j++) {
        float2 v = up2(a0[j]);
        v.x *= d0; v.y *= d0;
        sp0[j] = __float22half2_rn(v);
    }
    if (has1) {
        __half2* sp1 = reinterpret_cast<__half2*>(g_s + (long)n1 * 64 + half * 32);
#pragma unroll
        for (int j = 0; j < 16; j++) {
            float2 v = up2(a1[j]);
            v.x *= d1; v.y *= d1;
            sp1[j] = __float22half2_rn(v);
        }
    }
}

// --------------------------- CSR gather + relu epilogue --------------------
// h[v] = fp16(relu((s[v] + sum s[u]) * dis[v] + b)), 8 threads/node.
__device__ __forceinline__ void acc8(float2* a, uint4 p) {
    const __half2* h = reinterpret_cast<const __half2*>(&p);
#pragma unroll
    for (int q = 0; q < 4; q++) {
        float2 f = __half22float2(h[q]);
        a[q].x += f.x;
        a[q].y += f.y;
    }
}
__global__ void __launch_bounds__(256)
k_gather(const float* __restrict__ bias, int n) {
    int idx  = blockIdx.x * blockDim.x + threadIdx.x;
    int node = idx >> 3;
    int c    = idx & 7;
    if (node >= n) return;

    int beg = __ldg(g_rowptr + node);
    int end = __ldg(g_rowptr + node + 1);

    const uint4* s8 = reinterpret_cast<const uint4*>(g_s);
    float2 a[4] = {{0,0},{0,0},{0,0},{0,0}};
    acc8(a, s8[(long)node * 8 + c]);           // self loop

    int j = beg;
    for (; j + 4 <= end; j += 4) {
        int u0 = __ldg(g_csr + j);
        int u1 = __ldg(g_csr + j + 1);
        int u2 = __ldg(g_csr + j + 2);
        int u3 = __ldg(g_csr + j + 3);
        uint4 p0 = __ldg(s8 + (long)u0 * 8 + c);
        uint4 p1 = __ldg(s8 + (long)u1 * 8 + c);
        uint4 p2 = __ldg(s8 + (long)u2 * 8 + c);
        uint4 p3 = __ldg(s8 + (long)u3 * 8 + c);
        acc8(a, p0); acc8(a, p1); acc8(a, p2); acc8(a, p3);
    }
    for (; j < end; j++) {
        int u = __ldg(g_csr + j);
        acc8(a, __ldg(s8 + (long)u * 8 + c));
    }

    float dn = g_dis[node];
    float4 b0 = __ldg(reinterpret_cast<const float4*>(bias) + c * 2);
    float4 b1 = __ldg(reinterpret_cast<const float4*>(bias) + c * 2 + 1);

    __half2 out[4];
    out[0] = __floats2half2_rn(fmaxf(fmaf(a[0].x, dn, b0.x), 0.0f),
                               fmaxf(fmaf(a[0].y, dn, b0.y), 0.0f));
    out[1] = __floats2half2_rn(fmaxf(fmaf(a[1].x, dn, b0.z), 0.0f),
                               fmaxf(fmaf(a[1].y, dn, b0.w), 0.0f));
    out[2] = __floats2half2_rn(fmaxf(fmaf(a[2].x, dn, b1.x), 0.0f),
                               fmaxf(fmaf(a[2].y, dn, b1.y), 0.0f));
    out[3] = __floats2half2_rn(fmaxf(fmaf(a[3].x, dn, b1.z), 0.0f),
                               fmaxf(fmaf(a[3].y, dn, b1.w), 0.0f));
    reinterpret_cast<uint4*>(g_h)[(long)node * 8 + c] =
        *reinterpret_cast<uint4*>(out);
}

// --------------------------- pool ------------------------------------------
// pool[g][f] = sum of h[v][f] (relu already applied). Thread = (chunk c, lane r).
__global__ void __launch_bounds__(256)
k_pool(const int* __restrict__ gids, int n) {
    int t = threadIdx.x;
    int c = t & 7;
    int r = t >> 3;                            // 0..31
    int base = blockIdx.x * 256;
    int lim = base + 256 < n ? base + 256 : n;

    int cur = -1;
    float s[8] = {0, 0, 0, 0, 0, 0, 0, 0};
    for (int i = base + r; i < lim; i += 32) {
        int g = __ldg(gids + i);
        uint4 p = *reinterpret_cast<const uint4*>(g_h + (long)i * 64 + c * 8);
        const __half2* h = reinterpret_cast<const __half2*>(&p);
        float f[8];
#pragma unroll
        for (int q = 0; q < 4; q++) {
            float2 v = __half22float2(h[q]);
            f[2 * q] = v.x; f[2 * q + 1] = v.y;
        }
        if (g != cur) {
            if (cur >= 0)
#pragma unroll
                for (int q = 0; q < 8; q++)
                    atomicAdd(&g_pool[cur * 64 + c * 8 + q], s[q]);
            cur = g;
#pragma unroll
            for (int q = 0; q < 8; q++) s[q] = f[q];
        } else {
#pragma unroll
            for (int q = 0; q < 8; q++) s[q] += f[q];
        }
    }
    if (cur >= 0)
#pragma unroll
        for (int q = 0; q < 8; q++)
            atomicAdd(&g_pool[cur * 64 + c * 8 + q], s[q]);
}

// --------------------------- head MLP --------------------------------------
__global__ void k_head(const float* __restrict__ gfeat,
                       const float* __restrict__ gw, const float* __restrict__ gb,
                       const float* __restrict__ l1w, const float* __restrict__ l1b,
                       const float* __restrict__ l2w, const float* __restrict__ l2b,
                       const float* __restrict__ l3w, const float* __restrict__ l3b,
                       const float* __restrict__ l4w, const float* __restrict__ l4b,
                       float* __restrict__ out) {
    __shared__ float A[64][97];
    __shared__ float Bm[64][65];
    int t = threadIdx.x;

    for (int e = t; e < 64 * 64; e += 256) {          // z1
        int i = e >> 6, j = e & 63;
        float sum = l1b[j];
        for (int k = 0; k < 64; k++) sum = fmaf(g_pool[i * 64 + k], __ldg(l1w + k * 64 + j), sum);
        A[i][j] = fmaxf(sum, 0.0f);
    }
    for (int e = t; e < 64 * 32; e += 256) {          // gx
        int i = e >> 5, j = e & 31;
        float sum = gb[j];
        for (int k = 0; k < 32; k++) sum = fmaf(__ldg(gfeat + i * 32 + k), __ldg(gw + k * 32 + j), sum);
        A[i][64 + j] = fmaxf(sum, 0.0f);
    }
    __syncthreads();
    for (int e = t; e < 64 * 64; e += 256) {          // z2
        int i = e >> 6, j = e & 63;
        float sum = l2b[j];
        for (int k = 0; k < 96; k++) sum = fmaf(A[i][k], __ldg(l2w + k * 64 + j), sum);
        Bm[i][j] = fmaxf(sum, 0.0f);
    }
    __syncthreads();
    for (int e = t; e < 64 * 64; e += 256) {          // z3
        int i = e >> 6, j = e & 63;
        float sum = l3b[j];
        for (int k = 0; k < 64; k++) sum = fmaf(Bm[i][k], __ldg(l3w + k * 64 + j), sum);
        A[i][j] = fmaxf(sum, 0.0f);
    }
    __syncthreads();
    if (t < 64) {
        float sum = l4b[0];
        for (int k = 0; k < 64; k++) sum = fmaf(A[t][k], __ldg(l4w + k), sum);
        out[t] = sum;
    }
}

// ---------------------------------------------------------------------------
extern "C" void kernel_launch(void* const* d_in, const int* in_sizes, int n_in,
                              void* d_out, int out_size) {
    const float* x     = (const float*)d_in[0];
    const float* gfeat = (const float*)d_in[1];
    const float* cw[3] = {(const float*)d_in[2], (const float*)d_in[4], (const float*)d_in[6]};
    const float* cb[3] = {(const float*)d_in[3], (const float*)d_in[5], (const float*)d_in[7]};
    const float* l1w = (const float*)d_in[8];
    const float* l1b = (const float*)d_in[9];
    const float* gw  = (const float*)d_in[10];
    const float* gb  = (const float*)d_in[11];
    const float* l2w = (const float*)d_in[12];
    const float* l2b = (const float*)d_in[13];
    const float* l3w = (const float*)d_in[14];
    const float* l3b = (const float*)d_in[15];
    const float* l4w = (const float*)d_in[16];
    const float* l4b = (const float*)d_in[17];
    const int*   ei   = (const int*)d_in[18];
    const int*   gids = (const int*)d_in[19];
    float* out = (float*)d_out;

    int N = in_sizes[19];
    int E = in_sizes[18] / 2;
    const int* src = ei;
    const int* dst = ei + E;

    void* hp = nullptr;
    cudaGetSymbolAddress(&hp, g_h);
    const __half* h_in = (const __half*)hp;

    const int T = 256;
    int nb_n  = (N + T - 1) / T;
    int nb_e  = (E + T - 1) / T;
    int nb_e4 = (E / 4 + T - 1) / T;
    int nb_8n = (8 * N + T - 1) / T;

    cudaStream_t s1;
    cudaStreamCreate(&s1);
    cudaEvent_t e1, e2;
    cudaEventCreateWithFlags(&e1, cudaEventDisableTiming);
    cudaEventCreateWithFlags(&e2, cudaEventDisableTiming);

    // main chain: zero -> degc -> scan1
    k_zero <<<nb_n, T>>>(N);
    k_degc <<<nb_e4, T>>>(dst, E);
    k_scan1<<<nb_n, T>>>(N);
    cudaEventRecord(e1, 0);

    // side stream: gemm0 (needs only dis), overlapped with CSR finish
    cudaStreamWaitEvent(s1, e1, 0);
    k_gemm<true><<<nb_n, T, 0, s1>>>(x, nullptr, cw[0], N);
    cudaEventRecord(e2, s1);

    // main chain: finish CSR
    k_scan3<<<nb_n, T>>>(N, E);
    k_fill <<<nb_e, T>>>(src, dst, E);
    cudaStreamWaitEvent(0, e2, 0);

    // layers
    k_gather<<<nb_8n, T>>>(cb[0], N);
    k_gemm<false><<<nb_n, T>>>(nullptr, h_in, cw[1], N);
    k_gather<<<nb_8n, T>>>(cb[1], N);
    k_gemm<false><<<nb_n, T>>>(nullptr, h_in, cw[2], N);
    k_gather<<<nb_8n, T>>>(cb[2], N);

    // pool + head
    k_pool<<<nb_n, T>>>(gids, N);
    k_head<<<1, T>>>(gfeat, gw, gb, l1w, l1b, l2w, l2b, l3w, l3b, l4w, l4b, out);

    cudaEventDestroy(e1);
    cudaEventDestroy(e2);
    cudaStreamDestroy(s1);
}